// round 8
// baseline (speedup 1.0000x reference)
#include <cuda_runtime.h>
#include <cuda_bf16.h>
#include <cstdint>

// CelestialWaveAggregator via per-body scalar-function tabulation.
// After the ragged softmax aggregation, each body's MLP output is a smooth
// scalar function f_c(x). Kernel 1 computes f_c and f_c' (forward-mode AD)
// at 385 knots over [-8,8]. Kernel 2 converts knots -> per-segment cubic
// Hermite coefficients in smem (float4, one LDS.128 per eval), then streams
// the 62 MB input through a cp.async double-buffered persistent pipeline:
// ragged dot (<=12 FMA) + cubic Horner (3 FMA) per (pos, body).
// R7 delta: NSEG 256->384 (5x abs-error margin vs elementwise rel-err risk).

#define NB    13
#define NW    118
#define MAXW  12
#define NPOS  (32 * 4096)

#define NSEG   384
#define NKNOT  385
#define XMIN   (-8.0f)
#define SEG_H  (16.0f / 384.0f)
#define INV_H  24.0f

#define CHUNK  128              // positions per chunk
#define NCHUNK (NPOS / CHUNK)   // 1024
#define MGRID  148
#define MTPB   256

__constant__ int c_lens[NB]   = {9,9,9,9,9,9,9,9,9,9,12,8,3};
__constant__ int c_starts[NB] = {5,14,23,32,41,50,59,68,77,86,95,107,115};

__device__ float2 g_knots[NB * NKNOT];   // (f, f' * SEG_H) at each knot

// ---------------------------------------------------------------------------
__device__ __forceinline__ float gelu1(float v) {
    // exact (erf) GELU, matching jax.nn.gelu(approximate=False)
    return 0.5f * v * (1.0f + erff(v * 0.70710678118654752f));
}
__device__ __forceinline__ float gelup(float v) {
    // d/dv [v * Phi(v)] = Phi(v) + v * phi(v)
    float Phi = 0.5f * (1.0f + erff(v * 0.70710678118654752f));
    float phi = 0.3989422804014327f * __expf(-0.5f * v * v);
    return fmaf(v, phi, Phi);
}

// ---------------------------------------------------------------------------
// Kernel 1: knots (f, h*f') per (body, knot).
// block = 128 threads = 16 knots x 8 o-slices; grid = (25, 13).
__global__ __launch_bounds__(128)
void cwa_build_knots(const float* __restrict__ gW1, const float* __restrict__ gb1,
                     const float* __restrict__ gW2, const float* __restrict__ gb2,
                     const float* __restrict__ gW3, const float* __restrict__ gb3,
                     const float* __restrict__ gW4, const float* __restrict__ gb4)
{
    __shared__ float sW2T[64 * 33];     // [o][i], padded
    __shared__ float sW3 [64 * 33];     // [o][j], padded
    __shared__ float sW1[32], sb1[32], sb2[64], sb3[32], sW4[32];
    __shared__ float sb4;
    __shared__ float sh1 [16 * 33];     // [p][i]
    __shared__ float sh1d[16 * 33];
    __shared__ float red [16 * 8 * 33]; // [p][s][j]
    __shared__ float abuf[16 * 33];     // [p][j]
    __shared__ float adbuf[16 * 33];

    const int c   = blockIdx.y;
    const int tid = threadIdx.x;

    for (int idx = tid; idx < 2048; idx += 128) {
        int i = idx >> 6, o = idx & 63;        // gW2 flat = i*64+o
        sW2T[o * 33 + i] = gW2[c * 2048 + idx];
        int o3 = idx >> 5, j = idx & 31;       // gW3 flat = o*32+j
        sW3[o3 * 33 + j] = gW3[c * 2048 + idx];
    }
    if (tid < 32) {
        sW1[tid] = gW1[c * 32 + tid];
        sb1[tid] = gb1[c * 32 + tid];
        sb3[tid] = gb3[c * 32 + tid];
        sW4[tid] = gW4[c * 32 + tid];
    }
    if (tid >= 64 && tid < 128) sb2[tid - 64] = gb2[c * 64 + (tid - 64)];
    if (tid == 0) sb4 = gb4[c];
    __syncthreads();

    const int p = tid >> 3;              // knot within block (0..15)
    const int s = tid & 7;               // o-slice (0..7)
    int kn = blockIdx.x * 16 + p;
    if (kn > NSEG) kn = NSEG;            // clamp: duplicate work, no divergence
    const float x = XMIN + SEG_H * (float)kn;

    // layer1 values + derivatives (each thread does 4 of 32)
    #pragma unroll
    for (int k = 0; k < 4; k++) {
        int i = s * 4 + k;
        float v = fmaf(x, sW1[i], sb1[i]);
        sh1 [p * 33 + i] = gelu1(v);
        sh1d[p * 33 + i] = gelup(v) * sW1[i];
    }
    __syncthreads();

    // layer2 + layer3 partials over this thread's 8 o-values
    float pacc[32], paccd[32];
    #pragma unroll
    for (int j = 0; j < 32; j++) { pacc[j] = 0.f; paccd[j] = 0.f; }

    for (int k = 0; k < 8; k++) {
        const int o = s * 8 + k;
        float d = sb2[o], dd = 0.f;
        #pragma unroll
        for (int i = 0; i < 32; i++) {
            float w = sW2T[o * 33 + i];
            d  = fmaf(sh1 [p * 33 + i], w, d);
            dd = fmaf(sh1d[p * 33 + i], w, dd);
        }
        const float t  = gelu1(d);
        const float td = gelup(d) * dd;
        #pragma unroll
        for (int j = 0; j < 32; j++) {
            float w = sW3[o * 33 + j];
            pacc[j]  = fmaf(t,  w, pacc[j]);
            paccd[j] = fmaf(td, w, paccd[j]);
        }
    }

    // reduce the 8 slices: values
    #pragma unroll
    for (int j = 0; j < 32; j++) red[(p * 8 + s) * 33 + j] = pacc[j];
    __syncthreads();
    for (int q = tid; q < 512; q += 128) {
        int p2 = q >> 5, j = q & 31;
        float a = sb3[j];
        #pragma unroll
        for (int s2 = 0; s2 < 8; s2++) a += red[(p2 * 8 + s2) * 33 + j];
        abuf[p2 * 33 + j] = a;
    }
    __syncthreads();
    // derivatives
    #pragma unroll
    for (int j = 0; j < 32; j++) red[(p * 8 + s) * 33 + j] = paccd[j];
    __syncthreads();
    for (int q = tid; q < 512; q += 128) {
        int p2 = q >> 5, j = q & 31;
        float a = 0.f;
        #pragma unroll
        for (int s2 = 0; s2 < 8; s2++) a += red[(p2 * 8 + s2) * 33 + j];
        adbuf[p2 * 33 + j] = a;
    }
    __syncthreads();

    // layer3 gelu + layer4 + tanh (one thread per knot)
    if (tid < 16) {
        int kn2 = blockIdx.x * 16 + tid;
        if (kn2 <= NSEG) {
            float z = sb4, zd = 0.f;
            #pragma unroll
            for (int j = 0; j < 32; j++) {
                float a  = abuf[tid * 33 + j];
                float g  = gelu1(a);
                float gd = gelup(a) * adbuf[tid * 33 + j];
                z  = fmaf(g,  sW4[j], z);
                zd = fmaf(gd, sW4[j], zd);
            }
            float f  = tanhf(z);
            float fd = (1.0f - f * f) * zd;
            g_knots[c * NKNOT + kn2] = make_float2(f, fd * SEG_H);
        }
    }
}

// ---------------------------------------------------------------------------
// Kernel 2: persistent CTAs, cp.async double-buffered chunk pipeline.
// smem floats: buf0[15104] buf1[15104] coef[19968(=4992 f4)] wagg[156] sout[1664]
// total = 51996 floats = 203.1 KB < 227 KB carveout
#define BUF_F   (CHUNK * NW)          // 15104 floats
#define COEF_F  (NB * NSEG * 4)       // 19968 floats
#define OFF_BUF0 0
#define OFF_BUF1 BUF_F
#define OFF_COEF (2 * BUF_F)
#define OFF_WAGG (OFF_COEF + COEF_F)
#define OFF_SOUT (OFF_WAGG + NB * MAXW)
#define SMEM_FLOATS (OFF_SOUT + CHUNK * NB)
#define NCP   (BUF_F / 4)             // 3776 cp.async per chunk

__device__ __forceinline__ void cp_async16(uint32_t dst, const void* src) {
    asm volatile("cp.async.cg.shared.global [%0], [%1], 16;\n"
                 :: "r"(dst), "l"(src));
}
__device__ __forceinline__ void cp_commit() {
    asm volatile("cp.async.commit_group;\n");
}
template <int N>
__device__ __forceinline__ void cp_wait() {
    asm volatile("cp.async.wait_group %0;\n" :: "n"(N));
}

__device__ __forceinline__ void issue_chunk(uint32_t buf_saddr,
                                            const float* __restrict__ wf,
                                            int ch, int tid)
{
    const float4* src = (const float4*)(wf + (size_t)ch * BUF_F);
    #pragma unroll
    for (int k = 0; k < 15; k++) {
        int i = tid + k * MTPB;
        if (i < NCP) cp_async16(buf_saddr + i * 16, src + i);
    }
}

__global__ __launch_bounds__(MTPB, 1)
void cwa_main(const float* __restrict__ wf,
              const float* __restrict__ gl,
              float* __restrict__ out)
{
    extern __shared__ float sm[];
    float*  wagg = sm + OFF_WAGG;
    float*  sout = sm + OFF_SOUT;
    float4* coef = (float4*)(sm + OFF_COEF);

    const int tid = threadIdx.x;
    const uint32_t sbase = (uint32_t)__cvta_generic_to_shared(sm);

    // ---- prologue: fire first chunk load, then stage table/softmax ----
    int ch = blockIdx.x;
    if (ch < NCHUNK) {
        issue_chunk(sbase + OFF_BUF0 * 4, wf, ch, tid);
    }
    cp_commit();

    // per-body ragged softmax
    if (tid < NB) {
        const int len = c_lens[tid];
        float v[MAXW];
        float mx = -1e30f;
        for (int j = 0; j < len; j++) { v[j] = gl[tid * MAXW + j]; mx = fmaxf(mx, v[j]); }
        float ssum = 0.f;
        for (int j = 0; j < len; j++) { v[j] = expf(v[j] - mx); ssum += v[j]; }
        const float inv = 1.0f / ssum;
        for (int j = 0; j < MAXW; j++) wagg[tid * MAXW + j] = (j < len) ? v[j] * inv : 0.f;
    }

    // knots -> cubic Hermite coefficients (c0,c1,c2,c3) per (body, segment)
    {
        const float2* __restrict__ kn = g_knots;
        for (int seg = tid; seg < NB * NSEG; seg += MTPB) {
            const int c = seg / NSEG, i = seg - c * NSEG;
            const float2 k0 = __ldg(kn + c * NKNOT + i);
            const float2 k1 = __ldg(kn + c * NKNOT + i + 1);
            const float c2 = fmaf(3.0f, k1.x - k0.x, -2.0f * k0.y - k1.y);
            const float c3 = fmaf(2.0f, k0.x - k1.x,  k0.y + k1.y);
            coef[seg] = make_float4(k0.x, k0.y, c2, c3);
        }
    }

    // ---- main pipeline ----
    const int slice = tid & 1;
    const int pos   = tid >> 1;
    const int cbeg  = slice ? 7 : 0;
    const int cend  = slice ? 13 : 7;

    int cur = 0;
    for (; ch < NCHUNK; ch += MGRID) {
        const int nxt = ch + MGRID;
        if (nxt < NCHUNK) {
            issue_chunk(sbase + (cur ? OFF_BUF0 : OFF_BUF1) * 4, wf, nxt, tid);
            cp_commit();
            cp_wait<1>();
        } else {
            cp_commit();           // empty group keeps wait semantics uniform
            cp_wait<0>();
        }
        __syncthreads();           // data ready; also orders coef/wagg writes (iter 0)

        const float* row = sm + (cur ? OFF_BUF1 : OFF_BUF0) + pos * NW;
        for (int c = cbeg; c < cend; c++) {
            const int st = c_starts[c], ln = c_lens[c];
            float x = 0.f;
            for (int j = 0; j < ln; j++)
                x = fmaf(wagg[c * MAXW + j], row[st + j], x);
            float u = (x - XMIN) * INV_H;
            u = fminf(fmaxf(u, 0.0f), 383.999f);
            const int   i = (int)u;
            const float t = u - (float)i;
            const float4 cv = coef[c * NSEG + i];
            sout[pos * NB + c] =
                fmaf(fmaf(fmaf(cv.w, t, cv.z), t, cv.y), t, cv.x);
        }
        __syncthreads();           // LOAD-BEARING: block-wide compute done before
                                   // next iteration re-issues cp.async into the
                                   // buffer just read (WAR), and before sout store

        // coalesced store of this chunk's 128*13 outputs
        const float4* so4 = (const float4*)sout;
        float4* ob4 = (float4*)(out + (size_t)ch * (CHUNK * NB));
        #pragma unroll
        for (int i = tid; i < (CHUNK * NB) / 4; i += MTPB) ob4[i] = so4[i];

        cur ^= 1;
    }
}

// ---------------------------------------------------------------------------
extern "C" void kernel_launch(void* const* d_in, const int* in_sizes, int n_in,
                              void* d_out, int out_size)
{
    (void)in_sizes; (void)n_in; (void)out_size;
    const float* wf  = (const float*)d_in[0];
    const float* gl  = (const float*)d_in[1];
    const float* gW1 = (const float*)d_in[2];
    const float* gb1 = (const float*)d_in[3];
    const float* gW2 = (const float*)d_in[4];
    const float* gb2 = (const float*)d_in[5];
    const float* gW3 = (const float*)d_in[6];
    const float* gb3 = (const float*)d_in[7];
    const float* gW4 = (const float*)d_in[8];
    const float* gb4 = (const float*)d_in[9];
    float* out = (float*)d_out;

    // Idempotent, not a stream op (not captured); called every launch — the
    // harness forbids static guards / call-count checks.
    cudaFuncSetAttribute(cwa_main,
                         cudaFuncAttributeMaxDynamicSharedMemorySize,
                         SMEM_FLOATS * 4);

    dim3 bgrid((NKNOT + 15) / 16, NB);
    cwa_build_knots<<<bgrid, 128>>>(gW1, gb1, gW2, gb2, gW3, gb3, gW4, gb4);

    cwa_main<<<MGRID, MTPB, SMEM_FLOATS * 4>>>(wf, gl, out);
}